// round 7
// baseline (speedup 1.0000x reference)
#include <cuda_runtime.h>
#include <cstdint>

#define Bv 128
#define Nv 512
#define Xv 128
#define Hv 256
#define BN (Bv*Nv)           // 65536
#define GSZ (BN*Hv)          // 16777216 floats per gate buffer

// 6 precomputed gate-input buffers: 0=fg_x 1=ig_x 2=in_x 3=og_x 4=tm1 5=tm2
__device__ float g_pre[6][GSZ];

__device__ __forceinline__ float sigmoidf_(float v) { return 1.0f / (1.0f + __expf(-v)); }

// exp-based tanh: ~5 instr, rel err ~1e-6. Args bounded, no overflow path.
__device__ __forceinline__ float tanh_fast_(float x) {
    float e = __expf(-2.0f * x);
    return __fdividef(1.0f - e, 1.0f + e);
}

__device__ __forceinline__ uint32_t smem_u32_(const void* p) {
    uint32_t a;
    asm("{ .reg .u64 t; cvta.to.shared.u64 t, %1; cvt.u32.u64 %0, t; }" : "=r"(a) : "l"(p));
    return a;
}

// ---- f32x2 packed-math helpers (sm_100a) ----
__device__ __forceinline__ unsigned long long pack2_(float a) {
    unsigned long long r;
    asm("mov.b64 %0, {%1, %1};" : "=l"(r) : "f"(a));
    return r;
}
__device__ __forceinline__ void ffma2_(unsigned long long& d, unsigned long long a, unsigned long long b) {
    asm("fma.rn.f32x2 %0, %1, %2, %0;" : "+l"(d) : "l"(a), "l"(b));
}
__device__ __forceinline__ float upadd_(unsigned long long v) {
    float lo, hi;
    asm("mov.b64 {%0, %1}, %2;" : "=f"(lo), "=f"(hi) : "l"(v));
    return lo + hi;
}
__device__ __forceinline__ float2 unpack2_(unsigned long long v) {
    float lo, hi;
    asm("mov.b64 {%0, %1}, %2;" : "=f"(lo), "=f"(hi) : "l"(v));
    return make_float2(lo, hi);
}

// Bulk DSMEM copy: local smem src -> rank rk's smem dst (same offset),
// crediting rank rk's mbarrier with complete_tx bytes.
__device__ __forceinline__ void bulk_copy_rank_(uint32_t dst, uint32_t src,
                                                uint32_t mb, uint32_t rank,
                                                uint32_t bytes) {
    asm volatile(
        "{\n\t"
        ".reg .b32 rd, rm;\n\t"
        "mapa.shared::cluster.u32 rd, %0, %3;\n\t"
        "mapa.shared::cluster.u32 rm, %2, %3;\n\t"
        "cp.async.bulk.shared::cluster.shared::cta.mbarrier::complete_tx::bytes [rd], [%1], %4, [rm];\n\t"
        "}"
        :: "r"(dst), "r"(src), "r"(mb), "r"(rank), "r"(bytes) : "memory");
}

#define MBAR_INIT_(a, c) \
    asm volatile("mbarrier.init.shared.b64 [%0], %1;" :: "r"(a), "r"(c) : "memory")

#define MBAR_ARRIVE_EXPECT_(a, bytes) \
    asm volatile("mbarrier.arrive.expect_tx.shared.b64 _, [%0], %1;" \
                 :: "r"(a), "r"(bytes) : "memory")

#define FENCE_ASYNC_() asm volatile("fence.proxy.async.shared::cta;" ::: "memory")

__device__ __forceinline__ void mbar_wait_(uint32_t a, uint32_t parity) {
    asm volatile(
        "{\n\t"
        ".reg .pred P;\n\t"
        "WL_%=:\n\t"
        "mbarrier.try_wait.parity.acquire.cta.shared::cta.b64 P, [%0], %1, 0x989680;\n\t"
        "@P bra.uni WD_%=;\n\t"
        "bra.uni WL_%=;\n\t"
        "WD_%=:\n\t"
        "}"
        :: "r"(a), "r"(parity) : "memory");
}

#define CLUSTER_SYNC_() do { \
    asm volatile("barrier.cluster.arrive.aligned;" ::: "memory"); \
    asm volatile("barrier.cluster.wait.aligned;"   ::: "memory"); \
} while (0)

#define BAR_SYNC_(id, cnt) \
    asm volatile("bar.sync %0, %1;" :: "r"(id), "r"(cnt) : "memory")

// ============================================================================
// Phase 1: precompute all input-dependent gate terms. (unchanged)
// grid (512 bn-tiles, 24 h-tiles of 64), block 256, 2 CTAs/SM.
// ============================================================================

#define XS_STRIDE 132
#define WS_STRIDE 68
#define PRE_SMEM_BYTES ((128 * XS_STRIDE + 128 * WS_STRIDE) * 4)   // 102400

__global__ void __launch_bounds__(256, 2) precompute_kernel(
    const float* __restrict__ x, const float* __restrict__ tvec,
    const float* __restrict__ fg_w_x, const float* __restrict__ fg_b,
    const float* __restrict__ ig_w_x, const float* __restrict__ ig_b,
    const float* __restrict__ in_w_x, const float* __restrict__ in_b,
    const float* __restrict__ og_w_x, const float* __restrict__ og_b, const float* __restrict__ og_w_t,
    const float* __restrict__ tg1_w_x, const float* __restrict__ tg1_b, const float* __restrict__ tg1_w_t,
    const float* __restrict__ tg2_w_x, const float* __restrict__ tg2_b, const float* __restrict__ tg2_w_t)
{
    extern __shared__ float sm[];
    float* xs = sm;                        // [128][132]
    float* ws = sm + 128 * XS_STRIDE;      // [128 k][68]

    const int tid  = threadIdx.x;
    const int bn0  = blockIdx.x * 128;
    const int ht   = blockIdx.y;
    const int gate = ht >> 2;
    const int hl0  = (ht & 3) * 64;

    const float* wptr; const float* bptr; const float* tptr = nullptr;
    switch (gate) {
        case 0:  wptr = fg_w_x;  bptr = fg_b;  break;
        case 1:  wptr = ig_w_x;  bptr = ig_b;  break;
        case 2:  wptr = in_w_x;  bptr = in_b;  break;
        case 3:  wptr = og_w_x;  bptr = og_b;  tptr = og_w_t;  break;
        case 4:  wptr = tg1_w_x; bptr = tg1_b; tptr = tg1_w_t; break;
        default: wptr = tg2_w_x; bptr = tg2_b; tptr = tg2_w_t; break;
    }

    for (int i = tid; i < 4096; i += 256) {
        int row = i >> 5, kq = i & 31;
        *(float4*)(xs + row * XS_STRIDE + kq * 4) =
            *(const float4*)(x + (size_t)(bn0 + row) * 128 + kq * 4);
    }
    for (int i = tid; i < 2048; i += 256) {
        int h = i >> 5, kq = i & 31;
        float4 v = *(const float4*)(wptr + (size_t)(hl0 + h) * 128 + kq * 4);
        ws[(kq * 4 + 0) * WS_STRIDE + h] = v.x;
        ws[(kq * 4 + 1) * WS_STRIDE + h] = v.y;
        ws[(kq * 4 + 2) * WS_STRIDE + h] = v.z;
        ws[(kq * 4 + 3) * WS_STRIDE + h] = v.w;
    }
    __syncthreads();

    const int trow = tid >> 3;   // 0..31
    const int tcol = tid & 7;    // 0..7

    unsigned long long acc2[4][4];
    #pragma unroll
    for (int i = 0; i < 4; i++) {
        #pragma unroll
        for (int q = 0; q < 4; q++) acc2[i][q] = 0ull;
    }

    #pragma unroll 2
    for (int k4 = 0; k4 < 32; ++k4) {
        float4 av[4];
        #pragma unroll
        for (int i = 0; i < 4; i++)
            av[i] = *(const float4*)(xs + (trow * 4 + i) * XS_STRIDE + k4 * 4);
        #pragma unroll
        for (int cc = 0; cc < 4; cc++) {
            const float* wr = ws + (k4 * 4 + cc) * WS_STRIDE + tcol * 8;
            ulonglong2 b01 = *(const ulonglong2*)(wr);
            ulonglong2 b23 = *(const ulonglong2*)(wr + 4);
            #pragma unroll
            for (int i = 0; i < 4; i++) {
                float a = (cc == 0) ? av[i].x : (cc == 1) ? av[i].y
                        : (cc == 2) ? av[i].z : av[i].w;
                unsigned long long aa = pack2_(a);
                ffma2_(acc2[i][0], aa, b01.x);
                ffma2_(acc2[i][1], aa, b01.y);
                ffma2_(acc2[i][2], aa, b23.x);
                ffma2_(acc2[i][3], aa, b23.y);
            }
        }
    }

    const int hgbase = hl0 + tcol * 8;
    float bias[8], tw[8];
    #pragma unroll
    for (int jj = 0; jj < 8; jj++) {
        bias[jj] = bptr[hgbase + jj];
        tw[jj]   = (tptr != nullptr) ? tptr[hgbase + jj] : 0.0f;
    }
    float* outg = &g_pre[gate][0];
    #pragma unroll
    for (int i = 0; i < 4; i++) {
        int row = bn0 + trow * 4 + i;
        float tv = (gate >= 3) ? tvec[row] : 0.0f;
        float oo[8];
        #pragma unroll
        for (int q = 0; q < 4; q++) {
            float2 u = unpack2_(acc2[i][q]);
            oo[2 * q]     = u.x;
            oo[2 * q + 1] = u.y;
        }
        float o[8];
        #pragma unroll
        for (int jj = 0; jj < 8; jj++) {
            float v;
            if (gate < 3)       v = oo[jj] + bias[jj];
            else if (gate == 3) v = oo[jj] + tw[jj] * tv + bias[jj];
            else                v = sigmoidf_(oo[jj] + tanhf(tw[jj] * tv) + bias[jj]);
            o[jj] = v;
        }
        float4* dst = (float4*)(outg + (size_t)row * 256 + hgbase);
        dst[0] = make_float4(o[0], o[1], o[2], o[3]);
        dst[1] = make_float4(o[4], o[5], o[6], o[7]);
    }
}

// ============================================================================
// Phase 2: recurrence. 16 clusters x 8 CTAs x 1024 threads (32 warps, occ 50%).
// Rank r owns H-slice [32r,32r+32). Cluster rows [8c,8c+8) split:
//   group A = rows 0-3 on warps 0-15;  group B = rows 4-7 on warps 16-31.
// The two groups run CONCURRENTLY on disjoint warps with group-private
// barriers (bar.sync 1/2), mbarriers, reduction and staging buffers; each
// group's h-exchange latency is hidden by the other group's compute.
// Weights in SMEM (f32x2-paired): Wt4[k2*256 + gp*128 + j*4 + gl*2 + p].
// Per group-step per warp (k-chunk 16): 16 LDS.128 weights + 32 LDS.64 h
// (broadcast) + 128 FFMA2 -> red STS -> bar -> owner warps reduce + gates ->
// staging -> 8x 512B cp.async.bulk to all ranks with complete_tx.
// ============================================================================

#define REC_THREADS 1024
// smem float offsets
#define WT   0                 // 32768 floats (128 KB)
#define HBA  32768             // [2 par][8 r][4 b][32 j] = 2048
#define HBB  34816
#define STA  36864             // [2 par][128]
#define STB  37120
#define RDA  37376             // float2 [16 kc][4 b][2 gp][32 j] = 8192 floats
#define RDB  45568
#define MBo  53760             // 4 x u64 = 8 floats
#define SMEM_REC_BYTES ((MBo + 16) * 4)   // 215104 B

__global__ void __cluster_dims__(8, 1, 1) __launch_bounds__(REC_THREADS, 1) lstm_rec_kernel(
    const float* __restrict__ fg_w_c, const float* __restrict__ fg_w_h,
    const float* __restrict__ ig_w_c, const float* __restrict__ ig_w_h,
    const float* __restrict__ in_w_h,
    const float* __restrict__ og_w_cn, const float* __restrict__ og_w_h,
    float* __restrict__ out)
{
    extern __shared__ float sm[];
    const int tid = threadIdx.x;
    const int r   = blockIdx.x & 7;
    const int grp = blockIdx.x >> 3;
    const int j   = tid & 31;
    const int w   = tid >> 5;          // 0..31
    const int jg  = r * 32 + j;

    const uint32_t sbase = smem_u32_(sm);
    const uint32_t mbA0 = sbase + MBo * 4;
    const uint32_t mbA1 = mbA0 + 8;
    const uint32_t mbB0 = mbA0 + 16;
    const uint32_t mbB1 = mbA0 + 24;

    // Paired weight fill: Wt4[k2*256 + gp*128 + jj*4 + gl*2 + p] = W_g[r*32+jj][2*k2+p]
    for (int idx = tid; idx < 32768; idx += REC_THREADS) {
        int p  = idx & 1;
        int gl = (idx >> 1) & 1;
        int jj = (idx >> 2) & 31;
        int gp = (idx >> 7) & 1;
        int k2 = idx >> 8;
        int g  = gp * 2 + gl;
        const float* W = (g == 0) ? ig_w_h : (g == 1) ? fg_w_h
                       : (g == 2) ? in_w_h : og_w_h;
        sm[WT + idx] = W[(size_t)(r * 32 + jj) * 256 + (2 * k2 + p)];
    }
    // Zero both groups' h buffers (both parities): HBA..HBB+2048 contiguous
    for (int idx = tid; idx < 4096; idx += REC_THREADS) sm[HBA + idx] = 0.0f;

    if (tid == 0) {
        MBAR_INIT_(mbA0, 1); MBAR_INIT_(mbA1, 1);
        MBAR_INIT_(mbB0, 1); MBAR_INIT_(mbB1, 1);
        MBAR_ARRIVE_EXPECT_(mbA0, 4096); MBAR_ARRIVE_EXPECT_(mbA1, 4096);
        MBAR_ARRIVE_EXPECT_(mbB0, 4096); MBAR_ARRIVE_EXPECT_(mbB1, 4096);
    }

    const float wc_ig = ig_w_c[jg];
    const float wc_fg = fg_w_c[jg];
    const float wc_og = og_w_cn[jg];

    __syncthreads();
    CLUSTER_SYNC_();   // mbarriers + zeroed buffers visible before any copy

    const int inA  = (w < 16);
    const int wk   = inA ? w : (w - 16);          // warp index within group
    const int own  = (wk < 4);                    // owner warps: first 4 of group
    const int bO   = wk;                          // owner's batch row (if own)
    const int bg   = grp * 8 + (inA ? 0 : 4) + bO;
    const size_t rowoff = (size_t)bg * Nv * 256 + jg;

    // group-specific smem regions
    const int HB = inA ? HBA : HBB;
    const int ST = inA ? STA : STB;
    const int RD = inA ? RDA : RDB;
    const int barG = inA ? 1 : 2;      // full-group barrier id
    const int barO = inA ? 3 : 4;      // owner barrier id
    const uint32_t mbq0 = inA ? mbA0 : mbB0;
    const uint32_t mbq1 = inA ? mbA1 : mbB1;
    const int poster = inA ? 0 : 512;  // expect-reposting thread
    const int pusher0 = inA ? 0 : 512; // first of 8 copy-issuing threads

    float cmv = 0.0f, hnv = 0.0f;
    uint32_t ph0 = 0, ph1 = 0;

    // matmul geometry
    const float* wp0 = sm + WT + (wk * 8) * 256 + j * 4;
    const int hoff = ((wk >> 1) & 7) * 128 + (wk & 1) * 16;

    #pragma unroll 1
    for (int n = 0; n < Nv; ++n) {
        const int q = n & 1;

        if (n != 0) {
            const uint32_t mb = q ? mbq1 : mbq0;
            mbar_wait_(mb, q ? ph1 : ph0);
            if (q) ph1 ^= 1; else ph0 ^= 1;
            if (tid == poster) MBAR_ARRIVE_EXPECT_(mb, 4096);
        }

        float p0 = 0.f, p1 = 0.f, p2 = 0.f, p3 = 0.f, p4 = 0.f, p5 = 0.f;
        if (own) {
            const size_t off = rowoff + (size_t)n * 256;
            p0 = __ldcs(&g_pre[0][off]); p1 = __ldcs(&g_pre[1][off]);
            p2 = __ldcs(&g_pre[2][off]); p3 = __ldcs(&g_pre[3][off]);
            p4 = __ldcs(&g_pre[4][off]); p5 = __ldcs(&g_pre[5][off]);
        }

        // Matmul: k-chunk 16 (8 k-pairs), 4 batch rows, 4 gates.
        {
            const float* hc = sm + HB + q * 1024 + hoff;
            unsigned long long aig[4] = {0,0,0,0}, afg[4] = {0,0,0,0};
            unsigned long long ain[4] = {0,0,0,0}, aog[4] = {0,0,0,0};
            #pragma unroll
            for (int k2 = 0; k2 < 8; ++k2) {
                ulonglong2 wA = *(const ulonglong2*)(wp0 + k2 * 256);        // (ig, fg)
                ulonglong2 wB = *(const ulonglong2*)(wp0 + k2 * 256 + 128);  // (in, og)
                #pragma unroll
                for (int b = 0; b < 4; ++b) {
                    unsigned long long h2 = *(const unsigned long long*)(hc + b * 32 + 2 * k2);
                    ffma2_(aig[b], wA.x, h2);
                    ffma2_(afg[b], wA.y, h2);
                    ffma2_(ain[b], wB.x, h2);
                    ffma2_(aog[b], wB.y, h2);
                }
            }
            float2* red = (float2*)(sm + RD);
            #pragma unroll
            for (int b = 0; b < 4; ++b) {
                red[((wk * 4 + b) * 2 + 0) * 32 + j] = make_float2(upadd_(aig[b]), upadd_(afg[b]));
                red[((wk * 4 + b) * 2 + 1) * 32 + j] = make_float2(upadd_(ain[b]), upadd_(aog[b]));
            }
        }
        BAR_SYNC_(barG, 512);

        if (own) {
            const float2* red = (const float2*)(sm + RD);
            float s_ig = 0.f, s_fg = 0.f, s_in = 0.f, s_og = 0.f;
            #pragma unroll
            for (int kc = 0; kc < 16; kc++) {
                float2 v01 = red[((kc * 4 + bO) * 2 + 0) * 32 + j];
                float2 v23 = red[((kc * 4 + bO) * 2 + 1) * 32 + j];
                s_ig += v01.x; s_fg += v01.y; s_in += v23.x; s_og += v23.y;
            }
            float ig  = sigmoidf_(wc_ig * cmv + s_ig + p1);
            float fg  = sigmoidf_(wc_fg * cmv + s_fg + p0);
            float inn = tanh_fast_(s_in + p2);
            float fc  = fg * cmv;
            float gi  = ig * inn;
            float cmh = fc + gi * p4;
            cmv       = fc + gi * p5;
            float og  = sigmoidf_(wc_og * cmh + s_og + p3);
            hnv       = og * tanh_fast_(cmh);

            if (n < Nv - 1) sm[ST + (q ^ 1) * 128 + bO * 32 + j] = hnv;
            BAR_SYNC_(barO, 128);
            if (tid - pusher0 < 8 && n < Nv - 1) {
                FENCE_ASYNC_();
                bulk_copy_rank_(sbase + (HB + (q ^ 1) * 1024 + r * 128) * 4,
                                sbase + (ST + (q ^ 1) * 128) * 4,
                                (q ^ 1) ? mbq1 : mbq0,
                                (uint32_t)(tid - pusher0), 512);
            }
        }
    }

    CLUSTER_SYNC_();   // keep cluster resident until all copies consumed

    if (own) {
        out[(size_t)bg * 256 + jg]         = hnv;
        out[32768 + (size_t)bg * 256 + jg] = cmv;
    }
}

// ============================================================================
// Launch
// ============================================================================
extern "C" void kernel_launch(void* const* d_in, const int* in_sizes, int n_in,
                              void* d_out, int out_size)
{
    const float* x       = (const float*)d_in[0];
    const float* t       = (const float*)d_in[1];
    const float* fg_w_c  = (const float*)d_in[2];
    const float* fg_w_h  = (const float*)d_in[3];
    const float* fg_w_x  = (const float*)d_in[4];
    const float* fg_b    = (const float*)d_in[5];
    const float* ig_w_c  = (const float*)d_in[6];
    const float* ig_w_h  = (const float*)d_in[7];
    const float* ig_w_x  = (const float*)d_in[8];
    const float* ig_b    = (const float*)d_in[9];
    const float* in_w_h  = (const float*)d_in[10];
    const float* in_w_x  = (const float*)d_in[11];
    const float* in_b    = (const float*)d_in[12];
    const float* og_w_cn = (const float*)d_in[13];
    const float* og_w_h  = (const float*)d_in[14];
    const float* og_w_x  = (const float*)d_in[15];
    const float* og_b    = (const float*)d_in[16];
    const float* og_w_t  = (const float*)d_in[17];
    const float* tg1_w_x = (const float*)d_in[18];
    const float* tg1_w_t = (const float*)d_in[19];
    const float* tg1_b   = (const float*)d_in[20];
    const float* tg2_w_x = (const float*)d_in[21];
    const float* tg2_w_t = (const float*)d_in[22];
    const float* tg2_b   = (const float*)d_in[23];
    float* out = (float*)d_out;

    cudaFuncSetAttribute(precompute_kernel, cudaFuncAttributeMaxDynamicSharedMemorySize, PRE_SMEM_BYTES);
    cudaFuncSetAttribute(lstm_rec_kernel,   cudaFuncAttributeMaxDynamicSharedMemorySize, SMEM_REC_BYTES);

    dim3 gp(512, 24);
    precompute_kernel<<<gp, 256, PRE_SMEM_BYTES>>>(
        x, t,
        fg_w_x, fg_b, ig_w_x, ig_b, in_w_x, in_b,
        og_w_x, og_b, og_w_t,
        tg1_w_x, tg1_b, tg1_w_t,
        tg2_w_x, tg2_b, tg2_w_t);

    lstm_rec_kernel<<<128, REC_THREADS, SMEM_REC_BYTES>>>(
        fg_w_c, fg_w_h, ig_w_c, ig_w_h, in_w_h, og_w_cn, og_w_h, out);
}

// round 8
// speedup vs baseline: 1.4952x; 1.4952x over previous
#include <cuda_runtime.h>
#include <cuda_fp16.h>
#include <cstdint>

#define Bv 128
#define Nv 512
#define Xv 128
#define Hv 256
#define BN (Bv*Nv)           // 65536
#define GSZ (BN*Hv)          // 16777216 floats per gate buffer

// 6 precomputed gate-input buffers: 0=fg_x 1=ig_x 2=in_x 3=og_x 4=tm1 5=tm2
__device__ float g_pre[6][GSZ];

__device__ __forceinline__ float sigmoidf_(float v) { return 1.0f / (1.0f + __expf(-v)); }

// exp-based tanh: ~5 instr, rel err ~1e-6. Args bounded, no overflow path.
__device__ __forceinline__ float tanh_fast_(float x) {
    float e = __expf(-2.0f * x);
    return __fdividef(1.0f - e, 1.0f + e);
}

__device__ __forceinline__ uint32_t smem_u32_(const void* p) {
    uint32_t a;
    asm("{ .reg .u64 t; cvta.to.shared.u64 t, %1; cvt.u32.u64 %0, t; }" : "=r"(a) : "l"(p));
    return a;
}

// ---- f32x2 packed-math helpers (precompute kernel) ----
__device__ __forceinline__ unsigned long long pack2_(float a) {
    unsigned long long r;
    asm("mov.b64 %0, {%1, %1};" : "=l"(r) : "f"(a));
    return r;
}
__device__ __forceinline__ void ffma2_(unsigned long long& d, unsigned long long a, unsigned long long b) {
    asm("fma.rn.f32x2 %0, %1, %2, %0;" : "+l"(d) : "l"(a), "l"(b));
}
__device__ __forceinline__ float2 unpack2_(unsigned long long v) {
    float lo, hi;
    asm("mov.b64 {%0, %1}, %2;" : "=f"(lo), "=f"(hi) : "l"(v));
    return make_float2(lo, hi);
}

// ---- tensor-core helpers (rec kernel) ----
__device__ __forceinline__ void ldsm4t_(uint32_t* d, uint32_t addr) {
    asm volatile("ldmatrix.sync.aligned.m8n8.x4.trans.shared.b16 {%0,%1,%2,%3}, [%4];"
        : "=r"(d[0]), "=r"(d[1]), "=r"(d[2]), "=r"(d[3]) : "r"(addr));
}
__device__ __forceinline__ void mma16816_(float* c, const uint32_t* a, const uint32_t* b) {
    asm volatile(
        "mma.sync.aligned.m16n8k16.row.col.f32.f16.f16.f32 "
        "{%0,%1,%2,%3}, {%4,%5,%6,%7}, {%8,%9}, {%0,%1,%2,%3};"
        : "+f"(c[0]), "+f"(c[1]), "+f"(c[2]), "+f"(c[3])
        : "r"(a[0]), "r"(a[1]), "r"(a[2]), "r"(a[3]), "r"(b[0]), "r"(b[1]));
}
// Split fp32 pair into hi-fp16x2 and lo-residual-fp16x2.
__device__ __forceinline__ void split2_(float2 v, uint32_t& hi, uint32_t& lo) {
    __half h0 = __float2half_rn(v.x), h1 = __float2half_rn(v.y);
    float r0 = v.x - __half2float(h0), r1 = v.y - __half2float(h1);
    __half2 H = __halves2half2(h0, h1);
    __half2 L = __floats2half2_rn(r0, r1);
    hi = *(uint32_t*)&H;
    lo = *(uint32_t*)&L;
}

// Bulk DSMEM copy: local smem src -> rank rk's smem dst (same-offset address
// space), crediting rank rk's mbarrier with complete_tx bytes.
__device__ __forceinline__ void bulk_copy_rank_(uint32_t dst, uint32_t src,
                                                uint32_t mb, uint32_t rank,
                                                uint32_t bytes) {
    asm volatile(
        "{\n\t"
        ".reg .b32 rd, rm;\n\t"
        "mapa.shared::cluster.u32 rd, %0, %3;\n\t"
        "mapa.shared::cluster.u32 rm, %2, %3;\n\t"
        "cp.async.bulk.shared::cluster.shared::cta.mbarrier::complete_tx::bytes [rd], [%1], %4, [rm];\n\t"
        "}"
        :: "r"(dst), "r"(src), "r"(mb), "r"(rank), "r"(bytes) : "memory");
}

#define MBAR_INIT_(a, c) \
    asm volatile("mbarrier.init.shared.b64 [%0], %1;" :: "r"(a), "r"(c) : "memory")

#define MBAR_ARRIVE_EXPECT_(a, bytes) \
    asm volatile("mbarrier.arrive.expect_tx.shared.b64 _, [%0], %1;" \
                 :: "r"(a), "r"(bytes) : "memory")

#define FENCE_ASYNC_() asm volatile("fence.proxy.async.shared::cta;" ::: "memory")

__device__ __forceinline__ void mbar_wait_(uint32_t a, uint32_t parity) {
    asm volatile(
        "{\n\t"
        ".reg .pred P;\n\t"
        "WL_%=:\n\t"
        "mbarrier.try_wait.parity.acquire.cta.shared::cta.b64 P, [%0], %1, 0x989680;\n\t"
        "@P bra.uni WD_%=;\n\t"
        "bra.uni WL_%=;\n\t"
        "WD_%=:\n\t"
        "}"
        :: "r"(a), "r"(parity) : "memory");
}

#define CLUSTER_SYNC_() do { \
    asm volatile("barrier.cluster.arrive.aligned;" ::: "memory"); \
    asm volatile("barrier.cluster.wait.aligned;"   ::: "memory"); \
} while (0)

#define BAR_SYNC_(id, cnt) \
    asm volatile("bar.sync %0, %1;" :: "r"(id), "r"(cnt) : "memory")

// ============================================================================
// Phase 1: precompute all input-dependent gate terms. (unchanged from R6)
// grid (512 bn-tiles, 24 h-tiles of 64), block 256, 2 CTAs/SM.
// ============================================================================

#define XS_STRIDE 132
#define WS_STRIDE 68
#define PRE_SMEM_BYTES ((128 * XS_STRIDE + 128 * WS_STRIDE) * 4)   // 102400

__global__ void __launch_bounds__(256, 2) precompute_kernel(
    const float* __restrict__ x, const float* __restrict__ tvec,
    const float* __restrict__ fg_w_x, const float* __restrict__ fg_b,
    const float* __restrict__ ig_w_x, const float* __restrict__ ig_b,
    const float* __restrict__ in_w_x, const float* __restrict__ in_b,
    const float* __restrict__ og_w_x, const float* __restrict__ og_b, const float* __restrict__ og_w_t,
    const float* __restrict__ tg1_w_x, const float* __restrict__ tg1_b, const float* __restrict__ tg1_w_t,
    const float* __restrict__ tg2_w_x, const float* __restrict__ tg2_b, const float* __restrict__ tg2_w_t)
{
    extern __shared__ float sm[];
    float* xs = sm;                        // [128][132]
    float* ws = sm + 128 * XS_STRIDE;      // [128 k][68]

    const int tid  = threadIdx.x;
    const int bn0  = blockIdx.x * 128;
    const int ht   = blockIdx.y;
    const int gate = ht >> 2;
    const int hl0  = (ht & 3) * 64;

    const float* wptr; const float* bptr; const float* tptr = nullptr;
    switch (gate) {
        case 0:  wptr = fg_w_x;  bptr = fg_b;  break;
        case 1:  wptr = ig_w_x;  bptr = ig_b;  break;
        case 2:  wptr = in_w_x;  bptr = in_b;  break;
        case 3:  wptr = og_w_x;  bptr = og_b;  tptr = og_w_t;  break;
        case 4:  wptr = tg1_w_x; bptr = tg1_b; tptr = tg1_w_t; break;
        default: wptr = tg2_w_x; bptr = tg2_b; tptr = tg2_w_t; break;
    }

    for (int i = tid; i < 4096; i += 256) {
        int row = i >> 5, kq = i & 31;
        *(float4*)(xs + row * XS_STRIDE + kq * 4) =
            *(const float4*)(x + (size_t)(bn0 + row) * 128 + kq * 4);
    }
    for (int i = tid; i < 2048; i += 256) {
        int h = i >> 5, kq = i & 31;
        float4 v = *(const float4*)(wptr + (size_t)(hl0 + h) * 128 + kq * 4);
        ws[(kq * 4 + 0) * WS_STRIDE + h] = v.x;
        ws[(kq * 4 + 1) * WS_STRIDE + h] = v.y;
        ws[(kq * 4 + 2) * WS_STRIDE + h] = v.z;
        ws[(kq * 4 + 3) * WS_STRIDE + h] = v.w;
    }
    __syncthreads();

    const int trow = tid >> 3;   // 0..31
    const int tcol = tid & 7;    // 0..7

    unsigned long long acc2[4][4];
    #pragma unroll
    for (int i = 0; i < 4; i++) {
        #pragma unroll
        for (int q = 0; q < 4; q++) acc2[i][q] = 0ull;
    }

    #pragma unroll 2
    for (int k4 = 0; k4 < 32; ++k4) {
        float4 av[4];
        #pragma unroll
        for (int i = 0; i < 4; i++)
            av[i] = *(const float4*)(xs + (trow * 4 + i) * XS_STRIDE + k4 * 4);
        #pragma unroll
        for (int cc = 0; cc < 4; cc++) {
            const float* wr = ws + (k4 * 4 + cc) * WS_STRIDE + tcol * 8;
            ulonglong2 b01 = *(const ulonglong2*)(wr);
            ulonglong2 b23 = *(const ulonglong2*)(wr + 4);
            #pragma unroll
            for (int i = 0; i < 4; i++) {
                float a = (cc == 0) ? av[i].x : (cc == 1) ? av[i].y
                        : (cc == 2) ? av[i].z : av[i].w;
                unsigned long long aa = pack2_(a);
                ffma2_(acc2[i][0], aa, b01.x);
                ffma2_(acc2[i][1], aa, b01.y);
                ffma2_(acc2[i][2], aa, b23.x);
                ffma2_(acc2[i][3], aa, b23.y);
            }
        }
    }

    const int hgbase = hl0 + tcol * 8;
    float bias[8], tw[8];
    #pragma unroll
    for (int jj = 0; jj < 8; jj++) {
        bias[jj] = bptr[hgbase + jj];
        tw[jj]   = (tptr != nullptr) ? tptr[hgbase + jj] : 0.0f;
    }
    float* outg = &g_pre[gate][0];
    #pragma unroll
    for (int i = 0; i < 4; i++) {
        int row = bn0 + trow * 4 + i;
        float tv = (gate >= 3) ? tvec[row] : 0.0f;
        float oo[8];
        #pragma unroll
        for (int q = 0; q < 4; q++) {
            float2 u = unpack2_(acc2[i][q]);
            oo[2 * q]     = u.x;
            oo[2 * q + 1] = u.y;
        }
        float o[8];
        #pragma unroll
        for (int jj = 0; jj < 8; jj++) {
            float v;
            if (gate < 3)       v = oo[jj] + bias[jj];
            else if (gate == 3) v = oo[jj] + tw[jj] * tv + bias[jj];
            else                v = sigmoidf_(oo[jj] + tanhf(tw[jj] * tv) + bias[jj]);
            o[jj] = v;
        }
        float4* dst = (float4*)(outg + (size_t)row * 256 + hgbase);
        dst[0] = make_float4(o[0], o[1], o[2], o[3]);
        dst[1] = make_float4(o[4], o[5], o[6], o[7]);
    }
}

// ============================================================================
// Phase 2: recurrence via tensor cores (HMMA m16n8k16, split-precision fp16).
// 16 clusters x 8 CTAs x 512 threads (16 warps). Rank r: H-slice [32r,32r+32).
// Cluster rows [8c,8c+8) padded to M=16 (rows 8-15 zero).
// Warp grid: 4 k-groups (64 k each) x 4 n-slices (32 of 128 gate-outputs).
// Weights: B-fragments in REGISTERS, hi+lo fp16 split (64 regs/thread).
// h: dual fp16 planes (hi + residual lo), k-major [k 256][b 16] in SMEM,
// loaded with ldmatrix.x4.trans. 3 mma passes: Whi*Hhi + Whi*Hlo + Wlo*Hhi.
// 4-way k-reduction in SMEM -> gates fp32 (threads 0-255) -> h split to fp16
// staging -> 16x 1KB cp.async.bulk to all ranks' next-parity h planes with
// mbarrier complete_tx (expect 16 KB/step).
// ============================================================================

#define REC_THREADS 512
// byte offsets in dynamic smem
#define HBUF_B   0        // half [par 2][plane 2][k 256][b 16] = 32768 B
#define STG_B    32768    // half [par 2][plane 2][j 32][b 16] = 4096 B
#define CRED_B   36864    // float [kg 4][b 8][136] = 17408 B
#define MBAR_B   54272    // 2 x u64
#define SMEM_REC_BYTES 54400

__global__ void __cluster_dims__(8, 1, 1) __launch_bounds__(REC_THREADS, 1) lstm_rec_kernel(
    const float* __restrict__ fg_w_c, const float* __restrict__ fg_w_h,
    const float* __restrict__ ig_w_c, const float* __restrict__ ig_w_h,
    const float* __restrict__ in_w_h,
    const float* __restrict__ og_w_cn, const float* __restrict__ og_w_h,
    float* __restrict__ out)
{
    extern __shared__ char smc[];
    __half* Sg   = (__half*)(smc + STG_B);
    float*  Cred = (float*)(smc + CRED_B);

    const int tid  = threadIdx.x;
    const int lane = tid & 31;
    const int w    = tid >> 5;         // 0..15
    const int r    = blockIdx.x & 7;
    const int grp  = blockIdx.x >> 3;
    const int ns   = w & 3;            // n-slice (32 cols)
    const int kg   = w >> 2;           // k-group (64 k)

    const uint32_t sbase = smem_u32_(smc);
    const uint32_t mb0 = sbase + MBAR_B;
    const uint32_t mb1 = mb0 + 8;

    // ---- Load weight B-fragments into registers (hi + lo split) ----
    // n-col order: [ig | fg | in | og] x 32 j. B[k][n] = W_g[r*32 + (n&31)][k].
    uint32_t bh[4][4][2], bl[4][4][2];   // [nt][kt][pair]
    {
        const float* Wg0[4] = { ig_w_h, fg_w_h, in_w_h, og_w_h };
        #pragma unroll
        for (int nt = 0; nt < 4; nt++) {
            const int n  = ns * 32 + nt * 8 + (lane >> 2);
            const float* Wr = Wg0[n >> 5] + (size_t)(r * 32 + (n & 31)) * 256;
            #pragma unroll
            for (int kt = 0; kt < 4; kt++) {
                const int kb = kg * 64 + kt * 16 + (lane & 3) * 2;
                float2 v0 = *(const float2*)(Wr + kb);
                float2 v1 = *(const float2*)(Wr + kb + 8);
                split2_(v0, bh[nt][kt][0], bl[nt][kt][0]);
                split2_(v1, bh[nt][kt][1], bl[nt][kt][1]);
            }
        }
    }

    // Zero h buffers + staging (36864 B = 9216 words)
    for (int i = tid; i < 9216; i += REC_THREADS) ((uint32_t*)smc)[i] = 0u;

    if (tid == 0) {
        MBAR_INIT_(mb0, 1);
        MBAR_INIT_(mb1, 1);
        MBAR_ARRIVE_EXPECT_(mb0, 16384);
        MBAR_ARRIVE_EXPECT_(mb1, 16384);
    }

    // Owner-thread data (threads 0-255): b = tid>>5, j = lane
    const int b_own = w;               // valid when tid < 256
    const int j_own = lane;
    const int jg    = r * 32 + j_own;
    const int bg    = grp * 8 + b_own;
    const float wc_ig = ig_w_c[jg];
    const float wc_fg = fg_w_c[jg];
    const float wc_og = og_w_cn[jg];
    const size_t rowoff = (size_t)bg * Nv * 256 + jg;

    __syncthreads();
    CLUSTER_SYNC_();   // zeroed buffers + mbarriers visible to all ranks

    float cmv = 0.0f, hnv = 0.0f;
    uint32_t ph0 = 0, ph1 = 0;

    // ldmatrix per-lane addressing (k-major Ht[k][b], row = 32 B):
    const int krow_off = (lane & 7) + ((lane >> 4) << 3);
    const int bcol     = ((lane >> 3) & 1) << 3;

    #pragma unroll 1
    for (int n = 0; n < Nv; ++n) {
        const int q = n & 1;

        if (n != 0) {
            const uint32_t mb = q ? mb1 : mb0;
            mbar_wait_(mb, q ? ph1 : ph0);
            if (q) ph1 ^= 1; else ph0 ^= 1;
            if (tid == 0) MBAR_ARRIVE_EXPECT_(mb, 16384);
        }

        // Prefetch streamed gate terms (owners)
        float p0 = 0.f, p1 = 0.f, p2 = 0.f, p3 = 0.f, p4 = 0.f, p5 = 0.f;
        if (tid < 256) {
            const size_t off = rowoff + (size_t)n * 256;
            p0 = __ldcs(&g_pre[0][off]); p1 = __ldcs(&g_pre[1][off]);
            p2 = __ldcs(&g_pre[2][off]); p3 = __ldcs(&g_pre[3][off]);
            p4 = __ldcs(&g_pre[4][off]); p5 = __ldcs(&g_pre[5][off]);
        }

        // ---- Tensor-core matmul: 4 k-tiles x 4 n-tiles x 3 passes ----
        float c[4][4];
        #pragma unroll
        for (int nt = 0; nt < 4; nt++) { c[nt][0] = 0.f; c[nt][1] = 0.f; c[nt][2] = 0.f; c[nt][3] = 0.f; }

        #pragma unroll
        for (int kt = 0; kt < 4; kt++) {
            const uint32_t hbase = (uint32_t)(q * 8192 + (kg * 64 + kt * 16 + krow_off) * 16 + bcol);
            uint32_t ah[4], al[4];
            ldsm4t_(ah, sbase + HBUF_B + 2u * hbase);            // hi plane
            ldsm4t_(al, sbase + HBUF_B + 2u * (hbase + 4096));   // lo plane
            #pragma unroll
            for (int nt = 0; nt < 4; nt++) {
                mma16816_(c[nt], ah, bh[nt][kt]);
                mma16816_(c[nt], al, bh[nt][kt]);
                mma16816_(c[nt], ah, bl[nt][kt]);
            }
        }

        // Partials to SMEM (rows 0-7 only: c0,c1)
        {
            const int bq = lane >> 2;
            #pragma unroll
            for (int nt = 0; nt < 4; nt++) {
                const int n0 = ns * 32 + nt * 8 + (lane & 3) * 2;
                *(float2*)&Cred[(kg * 8 + bq) * 136 + n0] = make_float2(c[nt][0], c[nt][1]);
            }
        }
        __syncthreads();

        if (tid < 256) {
            // 4-way k-reduction: gate order n = [ig | fg | in | og]
            float s_ig = 0.f, s_fg = 0.f, s_in = 0.f, s_og = 0.f;
            #pragma unroll
            for (int kc = 0; kc < 4; kc++) {
                const float* rr = Cred + (kc * 8 + b_own) * 136 + j_own;
                s_ig += rr[0];
                s_fg += rr[32];
                s_in += rr[64];
                s_og += rr[96];
            }

            float ig  = sigmoidf_(wc_ig * cmv + s_ig + p1);
            float fg  = sigmoidf_(wc_fg * cmv + s_fg + p0);
            float inn = tanh_fast_(s_in + p2);
            float fc  = fg * cmv;
            float gi  = ig * inn;
            float cmh = fc + gi * p4;
            cmv       = fc + gi * p5;
            float og  = sigmoidf_(wc_og * cmh + s_og + p3);
            hnv       = og * tanh_fast_(cmh);

            if (n < Nv - 1) {
                const int qn = q ^ 1;
                __half hh = __float2half_rn(hnv);
                __half hl = __float2half_rn(hnv - __half2float(hh));
                Sg[qn * 1024 + 0 * 512 + j_own * 16 + b_own] = hh;
                Sg[qn * 1024 + 1 * 512 + j_own * 16 + b_own] = hl;
                BAR_SYNC_(1, 256);
                if (tid < 16) {
                    const uint32_t rk = (uint32_t)(tid & 7);
                    const uint32_t pl = (uint32_t)(tid >> 3);
                    FENCE_ASYNC_();
                    bulk_copy_rank_(
                        sbase + HBUF_B + 2u * (uint32_t)(qn * 8192 + pl * 4096 + (r * 32) * 16),
                        sbase + STG_B  + 2u * (uint32_t)(qn * 1024 + pl * 512),
                        qn ? mb1 : mb0, rk, 1024);
                }
            }
        }
    }

    CLUSTER_SYNC_();   // keep cluster resident until all copies consumed

    if (tid < 256) {
        out[(size_t)bg * 256 + jg]         = hnv;
        out[32768 + (size_t)bg * 256 + jg] = cmv;
    }
}

// ============================================================================
// Launch
// ============================================================================
extern "C" void kernel_launch(void* const* d_in, const int* in_sizes, int n_in,
                              void* d_out, int out_size)
{
    const float* x       = (const float*)d_in[0];
    const float* t       = (const float*)d_in[1];
    const float* fg_w_c  = (const float*)d_in[2];
    const float* fg_w_h  = (const float*)d_in[3];
    const float* fg_w_x  = (const float*)d_in[4];
    const float* fg_b    = (const float*)d_in[5];
    const float* ig_w_c  = (const float*)d_in[6];
    const float* ig_w_h  = (const float*)d_in[7];
    const float* ig_w_x  = (const float*)d_in[8];
    const float* ig_b    = (const float*)d_in[9];
    const float* in_w_h  = (const float*)d_in[10];
    const float* in_w_x  = (const float*)d_in[11];
    const float* in_b    = (const float*)d_in[12];
    const float* og_w_cn = (const float*)d_in[13];
    const float* og_w_h  = (const float*)d_in[14];
    const float* og_w_x  = (const float*)d_in[15];
    const float* og_b    = (const float*)d_in[16];
    const float* og_w_t  = (const float*)d_in[17];
    const float* tg1_w_x = (const float*)d_in[18];
    const float* tg1_w_t = (const float*)d_in[19];
    const float* tg1_b   = (const float*)d_in[20];
    const float* tg2_w_x = (const float*)d_in[21];
    const float* tg2_w_t = (const float*)d_in[22];
    const float* tg2_b   = (const float*)d_in[23];
    float* out = (float*)d_out;

    cudaFuncSetAttribute(precompute_kernel, cudaFuncAttributeMaxDynamicSharedMemorySize, PRE_SMEM_BYTES);
    cudaFuncSetAttribute(lstm_rec_kernel,   cudaFuncAttributeMaxDynamicSharedMemorySize, SMEM_REC_BYTES);

    dim3 gp(512, 24);
    precompute_kernel<<<gp, 256, PRE_SMEM_BYTES>>>(
        x, t,
        fg_w_x, fg_b, ig_w_x, ig_b, in_w_x, in_b,
        og_w_x, og_b, og_w_t,
        tg1_w_x, tg1_b, tg1_w_t,
        tg2_w_x, tg2_b, tg2_w_t);

    lstm_rec_kernel<<<128, REC_THREADS, SMEM_REC_BYTES>>>(
        fg_w_c, fg_w_h, ig_w_c, ig_w_h, in_w_h, og_w_cn, og_w_h, out);
}